// round 15
// baseline (speedup 1.0000x reference)
#include <cuda_runtime.h>
#include <cuda_bf16.h>
#include <cstdint>

#define DINLINE __device__ __forceinline__

constexpr int DIM = 4096;   // K
constexpr int SEQ = 4096;   // M
constexpr int OUT = 4096;   // N
constexpr int NKT = DIM / 128;   // 32 K-tiles of 128B

// Tile-major, XOR-swizzled operand buffers:
// tile(blk, kit) is a dense 16KB block at ((blk*NKT)+kit)<<14;
// inside: byte(row, k) at row*128 + ((k>>4 ^ (row&7))<<4) + (k&15)
__device__ __align__(1024) int8_t g_qx[(size_t)SEQ * DIM];
__device__ __align__(1024) int8_t g_wb[(size_t)OUT * DIM];
__device__ float g_rscale[SEQ];

// ---------------------------------------------------------------------------
DINLINE uint32_t smem_u32(const void* p) {
    uint32_t a;
    asm("{ .reg .u64 t; cvta.to.shared.u64 t, %1; cvt.u32.u64 %0, t; }" : "=r"(a) : "l"(p));
    return a;
}

#define MBAR_INIT(addr, cnt) \
    asm volatile("mbarrier.init.shared.b64 [%0], %1;" :: "r"(addr), "r"(cnt) : "memory")
#define MBAR_EXPECT_TX(addr, tx) \
    asm volatile("mbarrier.arrive.expect_tx.shared.b64 _, [%0], %1;" :: "r"(addr), "r"(tx) : "memory")
#define MBAR_ARRIVE(addr) \
    asm volatile("mbarrier.arrive.shared.b64 _, [%0];" :: "r"(addr) : "memory")
#define FENCE_PROXY_ASYNC() asm volatile("fence.proxy.async.shared::cta;" ::: "memory")

DINLINE void bulk_g2s(uint32_t dst, const void* src, uint32_t bytes, uint32_t mbar) {
    asm volatile(
        "cp.async.bulk.shared::cluster.global.mbarrier::complete_tx::bytes [%0], [%1], %2, [%3];"
        :: "r"(dst), "l"(src), "r"(bytes), "r"(mbar) : "memory");
}

DINLINE void mbar_wait(uint32_t mbar, uint32_t parity) {
    asm volatile(
        "{\n\t.reg .pred P;\n\t"
        "WL_%=:\n\t"
        "mbarrier.try_wait.parity.acquire.cta.shared::cta.b64 P, [%0], %1, 0x989680;\n\t"
        "@P bra.uni WD_%=;\n\t"
        "bra.uni WL_%=;\n\t"
        "WD_%=:\n\t}"
        :: "r"(mbar), "r"(parity) : "memory");
}

DINLINE void ldm_x4(uint32_t* r, uint32_t addr) {
    asm volatile("ldmatrix.sync.aligned.m8n8.x4.shared.b16 {%0,%1,%2,%3}, [%4];"
                 : "=r"(r[0]), "=r"(r[1]), "=r"(r[2]), "=r"(r[3]) : "r"(addr));
}

DINLINE void mma_s8(int* c, const uint32_t* a, const uint32_t* b) {
    asm volatile(
        "mma.sync.aligned.m16n8k32.row.col.s32.s8.s8.s32 "
        "{%0,%1,%2,%3}, {%4,%5,%6,%7}, {%8,%9}, {%0,%1,%2,%3};"
        : "+r"(c[0]), "+r"(c[1]), "+r"(c[2]), "+r"(c[3])
        : "r"(a[0]), "r"(a[1]), "r"(a[2]), "r"(a[3]), "r"(b[0]), "r"(b[1]));
}

// ---------------------------------------------------------------------------
// Fused prep: quant x rows + convert W rows into tile-major swizzled layout.
// ---------------------------------------------------------------------------
DINLINE int q1(float v, float s) {
    return (int)fminf(fmaxf(rintf(v * s), -128.f), 127.f);
}
DINLINE uint32_t qpack4(float4 v, float s) {
    uint32_t b0 = (uint32_t)q1(v.x, s) & 0xFF;
    uint32_t b1 = (uint32_t)q1(v.y, s) & 0xFF;
    uint32_t b2 = (uint32_t)q1(v.z, s) & 0xFF;
    uint32_t b3 = (uint32_t)q1(v.w, s) & 0xFF;
    return b0 | (b1 << 8) | (b2 << 16) | (b3 << 24);
}

__global__ void __launch_bounds__(256) prep_kernel(const float* __restrict__ x,
                                                   const float* __restrict__ W) {
    const int tid = threadIdx.x;
    const int kit = tid >> 3;          // k-tile 0..31
    const int seg = tid & 7;           // 16B segment within 128B row

    if (blockIdx.x < SEQ) {
        const int row = blockIdx.x;
        const float4* xr = reinterpret_cast<const float4*>(x) + (size_t)row * 1024 + tid * 4;

        float4 v[4];
        float m = 0.f;
#pragma unroll
        for (int i = 0; i < 4; i++) {
            v[i] = xr[i];
            m = fmaxf(m, fmaxf(fmaxf(fabsf(v[i].x), fabsf(v[i].y)),
                               fmaxf(fabsf(v[i].z), fabsf(v[i].w))));
        }
        __shared__ float red[8];
#pragma unroll
        for (int o = 16; o > 0; o >>= 1) m = fmaxf(m, __shfl_xor_sync(~0u, m, o));
        if ((tid & 31) == 0) red[tid >> 5] = m;
        __syncthreads();
        if (tid < 8) {
            float t = red[tid];
#pragma unroll
            for (int o = 4; o > 0; o >>= 1) t = fmaxf(t, __shfl_xor_sync(0xff, t, o));
            if (tid == 0) {
                float scale = 127.0f / fmaxf(t, 1e-5f);
                red[0] = scale;
                g_rscale[row] = 1.0f / scale;
            }
        }
        __syncthreads();
        const float scale = red[0];

        uint4 u;
        u.x = qpack4(v[0], scale);
        u.y = qpack4(v[1], scale);
        u.z = qpack4(v[2], scale);
        u.w = qpack4(v[3], scale);

        const int mblk = row >> 7, mrow = row & 127;
        size_t off = ((size_t)(mblk * NKT + kit) << 14) + mrow * 128 +
                     ((seg ^ (mrow & 7)) << 4);
        *reinterpret_cast<uint4*>(g_qx + off) = u;
    } else {
        const int row = blockIdx.x - SEQ;
        const float4* wr = reinterpret_cast<const float4*>(W) + (size_t)row * 1024 + tid * 4;
        uint4 u;
        uint32_t p[4];
#pragma unroll
        for (int i = 0; i < 4; i++) {
            float4 v = wr[i];
            uint32_t b0 = (uint32_t)(int)v.x & 0xFF;
            uint32_t b1 = (uint32_t)(int)v.y & 0xFF;
            uint32_t b2 = (uint32_t)(int)v.z & 0xFF;
            uint32_t b3 = (uint32_t)(int)v.w & 0xFF;
            p[i] = b0 | (b1 << 8) | (b2 << 16) | (b3 << 24);
        }
        u.x = p[0]; u.y = p[1]; u.z = p[2]; u.w = p[3];

        const int nblk = row >> 7, nrow = row & 127;
        size_t off = ((size_t)(nblk * NKT + kit) << 14) + nrow * 128 +
                     ((seg ^ (nrow & 7)) << 4);
        *reinterpret_cast<uint4*>(g_wb + off) = u;
    }
}

// ---------------------------------------------------------------------------
// int8 IMMA GEMM, CTA 128x128, 4 warps (warp 64x64), 3 smem stages,
// cp.async.bulk loads, full/empty mbarrier pipeline, fragment double-buffering
// across the 4 ks substeps. 2 CTAs/SM.
// ---------------------------------------------------------------------------
constexpr int MT = 128;
constexpr int NT = 128;
constexpr int STAGES = 3;
constexpr uint32_t TILE16K = 16384;
constexpr uint32_t STAGE_BYTES = 2 * TILE16K;                   // A + B = 32KB
constexpr uint32_t MBAR_OFF = STAGES * STAGE_BYTES;             // 98304
constexpr uint32_t SM_TOTAL = MBAR_OFF + 64;                    // full[3] + empty[3]

__global__ void __launch_bounds__(128, 2) gemm_kernel(const float* __restrict__ bias,
                                                      const float* __restrict__ wsp,
                                                      float* __restrict__ out) {
    extern __shared__ char smem[];
    const uint32_t sb = smem_u32(smem);
    const uint32_t mb_full  = sb + MBAR_OFF;        // 3 x 8B
    const uint32_t mb_empty = sb + MBAR_OFF + 24;   // 3 x 8B
    const int tid = threadIdx.x;
    const int lane = tid & 31;
    const int warp = tid >> 5;
    const int warp_m = warp & 1;
    const int warp_n = warp >> 1;
    const int m0 = blockIdx.y * MT;
    const int n0 = blockIdx.x * NT;

    const int8_t* const atiles = g_qx + ((size_t)blockIdx.y * NKT << 14);
    const int8_t* const btiles = g_wb + ((size_t)blockIdx.x * NKT << 14);

    auto issue_stage = [&](int j) {
        const uint32_t buf = (uint32_t)(j % STAGES);
        const uint32_t sa = sb + buf * STAGE_BYTES;
        const uint32_t mbar = mb_full + 8 * buf;
        MBAR_EXPECT_TX(mbar, STAGE_BYTES);
        bulk_g2s(sa,           atiles + ((size_t)j << 14), TILE16K, mbar);
        bulk_g2s(sa + TILE16K, btiles + ((size_t)j << 14), TILE16K, mbar);
    };

    if (tid == 0) {
#pragma unroll
        for (int s = 0; s < STAGES; s++) {
            MBAR_INIT(mb_full + 8 * s, 1);
            MBAR_INIT(mb_empty + 8 * s, 4);   // one arrive per warp
        }
    }
    __syncthreads();
    if (tid == 0) {
        FENCE_PROXY_ASYNC();
        issue_stage(0);
        issue_stage(1);
        issue_stage(2);
    }

    // ldmatrix addressing (validated mapping; XOR swizzle baked into gmem tiles)
    const int la7 = lane & 7;
    const int hiA = lane >> 4;
    const int hiB = (lane >> 3) & 1;
    const uint32_t rowA = (uint32_t)((warp_m * 64 + (lane & 7) + ((lane >> 3) & 1) * 8) * 128);
    const uint32_t rowB = (uint32_t)((warp_n * 64 + (lane & 7) + (lane >> 4) * 8) * 128);

    int acc[4][8][4];
#pragma unroll
    for (int tm = 0; tm < 4; tm++)
#pragma unroll
        for (int tn = 0; tn < 8; tn++)
#pragma unroll
            for (int r = 0; r < 4; r++) acc[tm][tn][r] = 0;

    // double-buffered fragments
    uint32_t af[2][4][4];
    uint32_t bf[2][8][2];

    auto load_frags = [&](int fb, uint32_t sA, uint32_t sB, int ks) {
        const uint32_t segA = (uint32_t)(((ks * 2 + hiA) ^ la7) << 4);
        const uint32_t segB = (uint32_t)(((ks * 2 + hiB) ^ la7) << 4);
#pragma unroll
        for (int tm = 0; tm < 4; tm++)
            ldm_x4(af[fb][tm], sA + rowA + tm * 2048 + segA);
#pragma unroll
        for (int j = 0; j < 4; j++) {
            uint32_t r[4];
            ldm_x4(r, sB + rowB + j * 2048 + segB);
            bf[fb][2 * j][0] = r[0]; bf[fb][2 * j][1] = r[1];
            bf[fb][2 * j + 1][0] = r[2]; bf[fb][2 * j + 1][1] = r[3];
        }
    };
    auto do_mmas = [&](int fb) {
#pragma unroll
        for (int tm = 0; tm < 4; tm++)
#pragma unroll
            for (int tn = 0; tn < 8; tn++)
                mma_s8(acc[tm][tn], af[fb][tm], bf[fb][tn]);
    };

    for (int i = 0; i < NKT; i++) {
        const uint32_t buf = (uint32_t)(i % STAGES);
        const uint32_t ph = (uint32_t)((i / STAGES) & 1);
        mbar_wait(mb_full + 8 * buf, ph);

        const uint32_t sA = sb + buf * STAGE_BYTES;
        const uint32_t sB = sA + TILE16K;

        load_frags(0, sA, sB, 0);
#pragma unroll
        for (int ks = 0; ks < 4; ks++) {
            if (ks < 3) load_frags((ks + 1) & 1, sA, sB, ks + 1);
            do_mmas(ks & 1);
        }

        // this warp is done reading buf: arrive on its empty barrier
        if (lane == 0) MBAR_ARRIVE(mb_empty + 8 * buf);

        // warp 0 (producer role): once all 4 warps are done with buf, refill it.
        if (warp == 0 && lane == 0 && i + STAGES < NKT) {
            mbar_wait(mb_empty + 8 * buf, ph);
            issue_stage(i + STAGES);
        }
    }

    // -------------------- epilogue --------------------
    const float inv_ws = 1.0f / wsp[0];
#pragma unroll
    for (int tm = 0; tm < 4; tm++) {
        const int r0 = m0 + warp_m * 64 + tm * 16 + (lane >> 2);
        const int r1 = r0 + 8;
        const float rs0 = g_rscale[r0];
        const float rs1 = g_rscale[r1];
        float* o0 = out + (size_t)r0 * OUT;
        float* o1 = out + (size_t)r1 * OUT;
#pragma unroll
        for (int tn = 0; tn < 8; tn++) {
            const int col = n0 + warp_n * 64 + tn * 8 + (lane & 3) * 2;
            const float b0v = bias[col], b1v = bias[col + 1];
            float2 v0, v1;
            v0.x = ((float)acc[tm][tn][0] * rs0 + b0v) * inv_ws;
            v0.y = ((float)acc[tm][tn][1] * rs0 + b1v) * inv_ws;
            v1.x = ((float)acc[tm][tn][2] * rs1 + b0v) * inv_ws;
            v1.y = ((float)acc[tm][tn][3] * rs1 + b1v) * inv_ws;
            *reinterpret_cast<float2*>(o0 + col) = v0;
            *reinterpret_cast<float2*>(o1 + col) = v1;
        }
    }
}

// ---------------------------------------------------------------------------
extern "C" void kernel_launch(void* const* d_in, const int* in_sizes, int n_in,
                              void* d_out, int out_size) {
    (void)in_sizes; (void)n_in; (void)out_size;
    const float* x    = (const float*)d_in[0];
    const float* W    = (const float*)d_in[1];
    const float* bias = (const float*)d_in[2];
    const float* ws   = (const float*)d_in[3];
    float* out = (float*)d_out;

    prep_kernel<<<SEQ + OUT, 256>>>(x, W);

    cudaFuncSetAttribute(gemm_kernel, cudaFuncAttributeMaxDynamicSharedMemorySize, SM_TOTAL);
    gemm_kernel<<<dim3(OUT / NT, SEQ / MT), 128, SM_TOTAL>>>(bias, ws, out);
}

// round 16
// speedup vs baseline: 1.0747x; 1.0747x over previous
#include <cuda_runtime.h>
#include <cuda_bf16.h>
#include <cstdint>

#define DINLINE __device__ __forceinline__

constexpr int DIM = 4096;   // K
constexpr int SEQ = 4096;   // M
constexpr int OUT = 4096;   // N
constexpr int NKT = DIM / 128;   // 32 K-tiles of 128B

// Tile-major, XOR-swizzled operand buffers:
// tile(blk, kit) is a dense 16KB block at ((blk*NKT)+kit)<<14;
// inside: byte(row, k) at row*128 + ((k>>4 ^ (row&7))<<4) + (k&15)
__device__ __align__(1024) int8_t g_qx[(size_t)SEQ * DIM];
__device__ __align__(1024) int8_t g_wb[(size_t)OUT * DIM];
__device__ float g_rscale[SEQ];

// ---------------------------------------------------------------------------
DINLINE uint32_t smem_u32(const void* p) {
    uint32_t a;
    asm("{ .reg .u64 t; cvta.to.shared.u64 t, %1; cvt.u32.u64 %0, t; }" : "=r"(a) : "l"(p));
    return a;
}

#define MBAR_INIT(addr, cnt) \
    asm volatile("mbarrier.init.shared.b64 [%0], %1;" :: "r"(addr), "r"(cnt) : "memory")
#define MBAR_EXPECT_TX(addr, tx) \
    asm volatile("mbarrier.arrive.expect_tx.shared.b64 _, [%0], %1;" :: "r"(addr), "r"(tx) : "memory")
#define MBAR_ARRIVE(addr) \
    asm volatile("mbarrier.arrive.shared.b64 _, [%0];" :: "r"(addr) : "memory")
#define FENCE_PROXY_ASYNC() asm volatile("fence.proxy.async.shared::cta;" ::: "memory")

DINLINE void bulk_g2s(uint32_t dst, const void* src, uint32_t bytes, uint32_t mbar) {
    asm volatile(
        "cp.async.bulk.shared::cluster.global.mbarrier::complete_tx::bytes [%0], [%1], %2, [%3];"
        :: "r"(dst), "l"(src), "r"(bytes), "r"(mbar) : "memory");
}

DINLINE void mbar_wait(uint32_t mbar, uint32_t parity) {
    asm volatile(
        "{\n\t.reg .pred P;\n\t"
        "WL_%=:\n\t"
        "mbarrier.try_wait.parity.acquire.cta.shared::cta.b64 P, [%0], %1, 0x989680;\n\t"
        "@P bra.uni WD_%=;\n\t"
        "bra.uni WL_%=;\n\t"
        "WD_%=:\n\t}"
        :: "r"(mbar), "r"(parity) : "memory");
}

DINLINE void ldm_x4(uint32_t* r, uint32_t addr) {
    asm volatile("ldmatrix.sync.aligned.m8n8.x4.shared.b16 {%0,%1,%2,%3}, [%4];"
                 : "=r"(r[0]), "=r"(r[1]), "=r"(r[2]), "=r"(r[3]) : "r"(addr));
}

DINLINE void mma_s8(int* c, const uint32_t* a, const uint32_t* b) {
    asm volatile(
        "mma.sync.aligned.m16n8k32.row.col.s32.s8.s8.s32 "
        "{%0,%1,%2,%3}, {%4,%5,%6,%7}, {%8,%9}, {%0,%1,%2,%3};"
        : "+r"(c[0]), "+r"(c[1]), "+r"(c[2]), "+r"(c[3])
        : "r"(a[0]), "r"(a[1]), "r"(a[2]), "r"(a[3]), "r"(b[0]), "r"(b[1]));
}

// ---------------------------------------------------------------------------
// Fused prep: quant x rows + convert W rows into tile-major swizzled layout.
// ---------------------------------------------------------------------------
DINLINE int q1(float v, float s) {
    return (int)fminf(fmaxf(rintf(v * s), -128.f), 127.f);
}
DINLINE uint32_t qpack4(float4 v, float s) {
    uint32_t b0 = (uint32_t)q1(v.x, s) & 0xFF;
    uint32_t b1 = (uint32_t)q1(v.y, s) & 0xFF;
    uint32_t b2 = (uint32_t)q1(v.z, s) & 0xFF;
    uint32_t b3 = (uint32_t)q1(v.w, s) & 0xFF;
    return b0 | (b1 << 8) | (b2 << 16) | (b3 << 24);
}

__global__ void __launch_bounds__(256) prep_kernel(const float* __restrict__ x,
                                                   const float* __restrict__ W) {
    const int tid = threadIdx.x;
    const int kit = tid >> 3;          // k-tile 0..31
    const int seg = tid & 7;           // 16B segment within 128B row

    if (blockIdx.x < SEQ) {
        const int row = blockIdx.x;
        const float4* xr = reinterpret_cast<const float4*>(x) + (size_t)row * 1024 + tid * 4;

        float4 v[4];
        float m = 0.f;
#pragma unroll
        for (int i = 0; i < 4; i++) {
            v[i] = xr[i];
            m = fmaxf(m, fmaxf(fmaxf(fabsf(v[i].x), fabsf(v[i].y)),
                               fmaxf(fabsf(v[i].z), fabsf(v[i].w))));
        }
        __shared__ float red[8];
#pragma unroll
        for (int o = 16; o > 0; o >>= 1) m = fmaxf(m, __shfl_xor_sync(~0u, m, o));
        if ((tid & 31) == 0) red[tid >> 5] = m;
        __syncthreads();
        if (tid < 8) {
            float t = red[tid];
#pragma unroll
            for (int o = 4; o > 0; o >>= 1) t = fmaxf(t, __shfl_xor_sync(0xff, t, o));
            if (tid == 0) {
                float scale = 127.0f / fmaxf(t, 1e-5f);
                red[0] = scale;
                g_rscale[row] = 1.0f / scale;
            }
        }
        __syncthreads();
        const float scale = red[0];

        uint4 u;
        u.x = qpack4(v[0], scale);
        u.y = qpack4(v[1], scale);
        u.z = qpack4(v[2], scale);
        u.w = qpack4(v[3], scale);

        const int mblk = row >> 7, mrow = row & 127;
        size_t off = ((size_t)(mblk * NKT + kit) << 14) + mrow * 128 +
                     ((seg ^ (mrow & 7)) << 4);
        *reinterpret_cast<uint4*>(g_qx + off) = u;
    } else {
        const int row = blockIdx.x - SEQ;
        const float4* wr = reinterpret_cast<const float4*>(W) + (size_t)row * 1024 + tid * 4;
        uint4 u;
        uint32_t p[4];
#pragma unroll
        for (int i = 0; i < 4; i++) {
            float4 v = wr[i];
            uint32_t b0 = (uint32_t)(int)v.x & 0xFF;
            uint32_t b1 = (uint32_t)(int)v.y & 0xFF;
            uint32_t b2 = (uint32_t)(int)v.z & 0xFF;
            uint32_t b3 = (uint32_t)(int)v.w & 0xFF;
            p[i] = b0 | (b1 << 8) | (b2 << 16) | (b3 << 24);
        }
        u.x = p[0]; u.y = p[1]; u.z = p[2]; u.w = p[3];

        const int nblk = row >> 7, nrow = row & 127;
        size_t off = ((size_t)(nblk * NKT + kit) << 14) + nrow * 128 +
                     ((seg ^ (nrow & 7)) << 4);
        *reinterpret_cast<uint4*>(g_wb + off) = u;
    }
}

// ---------------------------------------------------------------------------
// int8 IMMA GEMM, CTA 128x128, 8 warps (2x4, warp tile 64x32), 3 smem stages,
// cp.async.bulk loads, full/empty mbarrier pipeline. 2 CTAs/SM -> 4 warps/SMSP
// for stall cover on the tensor pipes.
// ---------------------------------------------------------------------------
constexpr int MT = 128;
constexpr int NT = 128;
constexpr int STAGES = 3;
constexpr uint32_t TILE16K = 16384;
constexpr uint32_t STAGE_BYTES = 2 * TILE16K;                   // A + B = 32KB
constexpr uint32_t MBAR_OFF = STAGES * STAGE_BYTES;             // 98304
constexpr uint32_t SM_TOTAL = MBAR_OFF + 64;                    // full[3] + empty[3]

__global__ void __launch_bounds__(256, 2) gemm_kernel(const float* __restrict__ bias,
                                                      const float* __restrict__ wsp,
                                                      float* __restrict__ out) {
    extern __shared__ char smem[];
    const uint32_t sb = smem_u32(smem);
    const uint32_t mb_full  = sb + MBAR_OFF;        // 3 x 8B
    const uint32_t mb_empty = sb + MBAR_OFF + 24;   // 3 x 8B
    const int tid = threadIdx.x;
    const int lane = tid & 31;
    const int warp = tid >> 5;        // 0..7
    const int warp_m = warp & 1;      // 2 warps along M (2*64 = 128)
    const int warp_n = warp >> 1;     // 4 warps along N (4*32 = 128)
    const int m0 = blockIdx.y * MT;
    const int n0 = blockIdx.x * NT;

    const int8_t* const atiles = g_qx + ((size_t)blockIdx.y * NKT << 14);
    const int8_t* const btiles = g_wb + ((size_t)blockIdx.x * NKT << 14);

    auto issue_stage = [&](int j) {
        const uint32_t buf = (uint32_t)(j % STAGES);
        const uint32_t sa = sb + buf * STAGE_BYTES;
        const uint32_t mbar = mb_full + 8 * buf;
        MBAR_EXPECT_TX(mbar, STAGE_BYTES);
        bulk_g2s(sa,           atiles + ((size_t)j << 14), TILE16K, mbar);
        bulk_g2s(sa + TILE16K, btiles + ((size_t)j << 14), TILE16K, mbar);
    };

    if (tid == 0) {
#pragma unroll
        for (int s = 0; s < STAGES; s++) {
            MBAR_INIT(mb_full + 8 * s, 1);
            MBAR_INIT(mb_empty + 8 * s, 8);   // one arrive per warp
        }
    }
    __syncthreads();
    if (tid == 0) {
        FENCE_PROXY_ASYNC();
        issue_stage(0);
        issue_stage(1);
        issue_stage(2);
    }

    // ldmatrix addressing (validated mapping; XOR swizzle baked into gmem tiles)
    const int la7 = lane & 7;
    const int hiA = lane >> 4;
    const int hiB = (lane >> 3) & 1;
    const uint32_t rowA = (uint32_t)((warp_m * 64 + (lane & 7) + ((lane >> 3) & 1) * 8) * 128);
    const uint32_t rowB = (uint32_t)((warp_n * 32 + (lane & 7) + (lane >> 4) * 8) * 128);

    int acc[4][4][4];
#pragma unroll
    for (int tm = 0; tm < 4; tm++)
#pragma unroll
        for (int tn = 0; tn < 4; tn++)
#pragma unroll
            for (int r = 0; r < 4; r++) acc[tm][tn][r] = 0;

    for (int i = 0; i < NKT; i++) {
        const uint32_t buf = (uint32_t)(i % STAGES);
        const uint32_t ph = (uint32_t)((i / STAGES) & 1);
        mbar_wait(mb_full + 8 * buf, ph);

        const uint32_t sA = sb + buf * STAGE_BYTES;
        const uint32_t sB = sA + TILE16K;
#pragma unroll
        for (int ks = 0; ks < 4; ks++) {
            const uint32_t segA = (uint32_t)(((ks * 2 + hiA) ^ la7) << 4);
            const uint32_t segB = (uint32_t)(((ks * 2 + hiB) ^ la7) << 4);
            uint32_t af[4][4];
#pragma unroll
            for (int tm = 0; tm < 4; tm++)
                ldm_x4(af[tm], sA + rowA + tm * 2048 + segA);
            uint32_t bf[4][2];
#pragma unroll
            for (int j = 0; j < 2; j++) {
                uint32_t r[4];
                ldm_x4(r, sB + rowB + j * 2048 + segB);
                bf[2 * j][0] = r[0]; bf[2 * j][1] = r[1];
                bf[2 * j + 1][0] = r[2]; bf[2 * j + 1][1] = r[3];
            }
#pragma unroll
            for (int tm = 0; tm < 4; tm++)
#pragma unroll
                for (int tn = 0; tn < 4; tn++)
                    mma_s8(acc[tm][tn], af[tm], bf[tn]);
        }

        // this warp is done reading buf: arrive on its empty barrier
        if (lane == 0) MBAR_ARRIVE(mb_empty + 8 * buf);

        // warp 0 (producer role): once all 8 warps are done with buf, refill it.
        if (warp == 0 && lane == 0 && i + STAGES < NKT) {
            mbar_wait(mb_empty + 8 * buf, ph);
            issue_stage(i + STAGES);
        }
    }

    // -------------------- epilogue --------------------
    const float inv_ws = 1.0f / wsp[0];
#pragma unroll
    for (int tm = 0; tm < 4; tm++) {
        const int r0 = m0 + warp_m * 64 + tm * 16 + (lane >> 2);
        const int r1 = r0 + 8;
        const float rs0 = g_rscale[r0];
        const float rs1 = g_rscale[r1];
        float* o0 = out + (size_t)r0 * OUT;
        float* o1 = out + (size_t)r1 * OUT;
#pragma unroll
        for (int tn = 0; tn < 4; tn++) {
            const int col = n0 + warp_n * 32 + tn * 8 + (lane & 3) * 2;
            const float b0v = bias[col], b1v = bias[col + 1];
            float2 v0, v1;
            v0.x = ((float)acc[tm][tn][0] * rs0 + b0v) * inv_ws;
            v0.y = ((float)acc[tm][tn][1] * rs0 + b1v) * inv_ws;
            v1.x = ((float)acc[tm][tn][2] * rs1 + b0v) * inv_ws;
            v1.y = ((float)acc[tm][tn][3] * rs1 + b1v) * inv_ws;
            *reinterpret_cast<float2*>(o0 + col) = v0;
            *reinterpret_cast<float2*>(o1 + col) = v1;
        }
    }
}

// ---------------------------------------------------------------------------
extern "C" void kernel_launch(void* const* d_in, const int* in_sizes, int n_in,
                              void* d_out, int out_size) {
    (void)in_sizes; (void)n_in; (void)out_size;
    const float* x    = (const float*)d_in[0];
    const float* W    = (const float*)d_in[1];
    const float* bias = (const float*)d_in[2];
    const float* ws   = (const float*)d_in[3];
    float* out = (float*)d_out;

    prep_kernel<<<SEQ + OUT, 256>>>(x, W);

    cudaFuncSetAttribute(gemm_kernel, cudaFuncAttributeMaxDynamicSharedMemorySize, SM_TOTAL);
    gemm_kernel<<<dim3(OUT / NT, SEQ / MT), 256, SM_TOTAL>>>(bias, ws, out);
}